// round 17
// baseline (speedup 1.0000x reference)
#include <cuda_runtime.h>
#include <cuda_fp16.h>
#include <math.h>
#include <stdint.h>

#define S   2048
#define D   1024
#define H   16
#define HD  64
#define MM  4096
#define LAY 4
#define QKVW 3072
// per-layer fp16 weight block offsets (halves)
#define WT_QKV   0u
#define WT_WO    3145728u
#define WT_W1    4194304u
#define WT_W2    8388608u
#define WT_LAYER 12582912u

// ---------------- scratch (device globals) ----------------
__device__ float g_x[S * D];
__device__ __half g_a3[S * D];
__device__ __half g_y3[S * MM];
__device__ __half g_wT[4 * WT_LAYER];
__device__ __half g_q[H * S * 64];   // [h][s][64] (scaled 1/8)
__device__ __half g_k[H * S * 64];
__device__ __half g_v[H * S * 64];

// ================= PTX helpers =================
#define GDC_WAIT()    asm volatile("griddepcontrol.wait;" ::: "memory")
#define GDC_TRIGGER() asm volatile("griddepcontrol.launch_dependents;" ::: "memory")

__device__ __forceinline__ uint32_t smem_u32(const void* p) {
    uint32_t a;
    asm("{ .reg .u64 t; cvta.to.shared.u64 t, %1; cvt.u32.u64 %0, t; }" : "=r"(a) : "l"(p));
    return a;
}
__device__ __forceinline__ void cp16(uint32_t saddr, const void* g) {
    asm volatile("cp.async.cg.shared.global [%0], [%1], 16;" :: "r"(saddr), "l"(g));
}
#define CP_COMMIT() asm volatile("cp.async.commit_group;" ::: "memory")
#define CP_WAIT1()  asm volatile("cp.async.wait_group 1;" ::: "memory")

__device__ __forceinline__ void ldsm4(uint32_t* r, uint32_t a) {
    asm volatile("ldmatrix.sync.aligned.m8n8.x4.shared.b16 {%0,%1,%2,%3}, [%4];"
                 : "=r"(r[0]), "=r"(r[1]), "=r"(r[2]), "=r"(r[3]) : "r"(a));
}
__device__ __forceinline__ void ldsm4t(uint32_t* r, uint32_t a) {
    asm volatile("ldmatrix.sync.aligned.m8n8.x4.trans.shared.b16 {%0,%1,%2,%3}, [%4];"
                 : "=r"(r[0]), "=r"(r[1]), "=r"(r[2]), "=r"(r[3]) : "r"(a));
}
__device__ __forceinline__ void mma16816(float* c, const uint32_t* a, uint32_t b0, uint32_t b1) {
    asm volatile("mma.sync.aligned.m16n8k16.row.col.f32.f16.f16.f32 "
                 "{%0,%1,%2,%3}, {%4,%5,%6,%7}, {%8,%9}, {%0,%1,%2,%3};"
                 : "+f"(c[0]), "+f"(c[1]), "+f"(c[2]), "+f"(c[3])
                 : "r"(a[0]), "r"(a[1]), "r"(a[2]), "r"(a[3]), "r"(b0), "r"(b1));
}

// ---------------- embedding + sinusoidal positional encoding ----------------
__global__ __launch_bounds__(256) void embed_kernel(const int* __restrict__ ids,
                                                    const float* __restrict__ emb,
                                                    float* __restrict__ x) {
    GDC_WAIT();
    GDC_TRIGGER();
    int s = blockIdx.x;
    int id = ids[s];
    const double c = -9.210340371976184 / 1024.0;
    for (int d = threadIdx.x; d < D; d += 256) {
        int p2 = d & ~1;
        double freq = exp((double)p2 * c);
        double phase = (double)s * freq;
        double pe = (d & 1) ? cos(phase) : sin(phase);
        x[s * D + d] = emb[id * D + d] + (float)pe;
    }
}

// ---------------- LayerNorm -> fp32 out (final) ----------------
__global__ __launch_bounds__(256) void ln_kernel(const float* __restrict__ x,
                                                 const float* __restrict__ sc,
                                                 const float* __restrict__ bi,
                                                 float* __restrict__ out) {
    GDC_WAIT();
    GDC_TRIGGER();
    __shared__ float ssum[256], ssq[256];
    int s = blockIdx.x, tid = threadIdx.x;
    float4 v = ((const float4*)(x + s * D))[tid];
    ssum[tid] = v.x + v.y + v.z + v.w;
    ssq[tid]  = v.x * v.x + v.y * v.y + v.z * v.z + v.w * v.w;
    __syncthreads();
#pragma unroll
    for (int off = 128; off > 0; off >>= 1) {
        if (tid < off) { ssum[tid] += ssum[tid + off]; ssq[tid] += ssq[tid + off]; }
        __syncthreads();
    }
    float mu  = ssum[0] * (1.0f / 1024.0f);
    float var = ssq[0] * (1.0f / 1024.0f) - mu * mu;
    float rs  = rsqrtf(var + 1e-6f);
    float4 scv = ((const float4*)sc)[tid];
    float4 biv = ((const float4*)bi)[tid];
    float4 o;
    o.x = (v.x - mu) * rs * scv.x + biv.x;
    o.y = (v.y - mu) * rs * scv.y + biv.y;
    o.z = (v.z - mu) * rs * scv.z + biv.z;
    o.w = (v.w - mu) * rs * scv.w + biv.w;
    ((float4*)(out + s * D))[tid] = o;
}

// ---------------- LayerNorm -> fp16 into a3 ----------------
__global__ __launch_bounds__(256) void ln_half_kernel(const float* __restrict__ x,
                                                      const float* __restrict__ sc,
                                                      const float* __restrict__ bi,
                                                      __half* __restrict__ a3) {
    GDC_WAIT();
    GDC_TRIGGER();
    __shared__ float ssum[256], ssq[256];
    int s = blockIdx.x, tid = threadIdx.x;
    float4 v = ((const float4*)(x + s * D))[tid];
    ssum[tid] = v.x + v.y + v.z + v.w;
    ssq[tid]  = v.x * v.x + v.y * v.y + v.z * v.z + v.w * v.w;
    __syncthreads();
#pragma unroll
    for (int off = 128; off > 0; off >>= 1) {
        if (tid < off) { ssum[tid] += ssum[tid + off]; ssq[tid] += ssq[tid + off]; }
        __syncthreads();
    }
    float mu  = ssum[0] * (1.0f / 1024.0f);
    float var = ssq[0] * (1.0f / 1024.0f) - mu * mu;
    float rs  = rsqrtf(var + 1e-6f);
    float4 scv = ((const float4*)sc)[tid];
    float4 biv = ((const float4*)bi)[tid];
    __half h0 = __float2half_rn((v.x - mu) * rs * scv.x + biv.x);
    __half h1 = __float2half_rn((v.y - mu) * rs * scv.y + biv.y);
    __half h2 = __float2half_rn((v.z - mu) * rs * scv.z + biv.z);
    __half h3 = __float2half_rn((v.w - mu) * rs * scv.w + biv.w);
    __half* orow = a3 + (size_t)s * D + tid * 4;
    *(__half2*)(orow)     = __halves2half2(h0, h1);
    *(__half2*)(orow + 2) = __halves2half2(h2, h3);
}

// ---- weight conversion, ALL layers: z = layer*4 + w; w in {wq,wk,wv,wo} ----
__global__ __launch_bounds__(256) void convW4_all(const float* __restrict__ wq,
                                                  const float* __restrict__ wk,
                                                  const float* __restrict__ wv,
                                                  const float* __restrict__ wo,
                                                  __half* __restrict__ wT) {
    GDC_WAIT();
    GDC_TRIGGER();
    __shared__ float t[32][33];
    int z = blockIdx.z, layer = z >> 2, w = z & 3;
    const float* W = ((w == 0) ? wq : (w == 1) ? wk : (w == 2) ? wv : wo)
                     + (size_t)layer * D * D;
    __half* base = wT + (size_t)layer * WT_LAYER + (w < 3 ? WT_QKV : WT_WO);
    int noff = (w < 3) ? w * 1024 : 0;
    const int K = D, N = D;
    int k0 = blockIdx.x * 32, n0 = blockIdx.y * 32;
    int tx = threadIdx.x & 31, ty = threadIdx.x >> 5;
#pragma unroll
    for (int i = 0; i < 4; i++)
        t[ty + i * 8][tx] = W[(size_t)(k0 + ty + i * 8) * N + n0 + tx];
    __syncthreads();
#pragma unroll
    for (int i = 0; i < 4; i++) {
        int n = n0 + ty + i * 8 + noff, k = k0 + tx;
        base[(size_t)n * K + k] = __float2half_rn(t[tx][ty + i * 8]);
    }
}
// ---- w1/w2, ALL layers: blockIdx.y = layer*2 + w ----
__global__ __launch_bounds__(256) void convW12_all(const float* __restrict__ w1,
                                                   const float* __restrict__ w2,
                                                   __half* __restrict__ wT) {
    GDC_WAIT();
    GDC_TRIGGER();
    __shared__ float t[32][33];
    int zy = blockIdx.y, layer = zy >> 1, w = zy & 1;
    const float* W = (w ? w2 : w1) + (size_t)layer * D * MM;
    __half* Wt = wT + (size_t)layer * WT_LAYER + (w ? WT_W2 : WT_W1);
    const int K = w ? MM : D, N = w ? D : MM;
    int bx = blockIdx.x;
    int kb = w ? (bx & 127) : (bx & 31);
    int nb = w ? (bx >> 7)  : (bx >> 5);
    int k0 = kb * 32, n0 = nb * 32;
    int tx = threadIdx.x & 31, ty = threadIdx.x >> 5;
#pragma unroll
    for (int i = 0; i < 4; i++)
        t[ty + i * 8][tx] = W[(size_t)(k0 + ty + i * 8) * N + n0 + tx];
    __syncthreads();
#pragma unroll
    for (int i = 0; i < 4; i++) {
        int n = n0 + ty + i * 8, k = k0 + tx;
        Wt[(size_t)n * K + k] = __float2half_rn(t[tx][ty + i * 8]);
    }
}

// ---- HMMA fp16 GEMM: MTx128 CTA, 256 threads, 2 CTAs/SM, BK=64, 3 stages ----
// MODE 0: fp32 C (+bias/relu/residual). MODE 1: fp16 into Cs [M,N].
// MODE 2: qkv scatter into g_q/g_k/g_v per-head fp16 buffers.
template<int MT, int MODE>
__global__ __launch_bounds__(256, 2) void gemm_tpl(const __half* __restrict__ A,
                                                   const __half* __restrict__ Bt,
                                                   float* __restrict__ C,
                                                   __half* __restrict__ Cs,
                                                   int N, int K,
                                                   const float* __restrict__ bias,
                                                   const float* residual, int relu) {
    extern __shared__ char sm[];
    constexpr int WTM = MT / 2;
    constexpr int FM = WTM / 16;
    constexpr int ROWB = 144;
    constexpr int STAGE = (MT + 128) * ROWB;
    const int tid = threadIdx.x, lane = tid & 31, wid = tid >> 5;
    const int bm = blockIdx.y * MT, bn = blockIdx.x * 128;
    const int wm = (wid >> 2) * WTM, wn = (wid & 3) * 32;
    const size_t rs = (size_t)K * 2;
    const char* Ag = (const char*)A + (size_t)bm * rs;
    const char* Bg = (const char*)Bt + (size_t)bn * rs;
    const uint32_t smb = smem_u32(sm);

    GDC_WAIT();

    uint32_t a_off[FM], b_off[2];
#pragma unroll
    for (int f = 0; f < FM; f++)
        a_off[f] = (uint32_t)((wm + f * 16 + (lane & 15)) * ROWB + ((lane >> 4) * 16));
#pragma unroll
    for (int pi = 0; pi < 2; pi++) {
        int row = wn + pi * 16 + (lane & 7) + ((lane >> 4) << 3);
        b_off[pi] = (uint32_t)(row * ROWB + (((lane >> 3) & 1) * 16));
    }

    float acc[FM][4][4];
#pragma unroll
    for (int f = 0; f < FM; f++)
#pragma unroll
        for (int ni = 0; ni < 4; ni++)
#pragma unroll
            for (int j = 0; j < 4; j++) acc[f][ni][j] = 0.0f;

    auto load_stage = [&](int buf, int kt) {
        uint32_t sa = smb + buf * STAGE, sb2 = sa + MT * ROWB;
        size_t gk = (size_t)kt * 128;
#pragma unroll
        for (int i = 0; i < MT / 32; i++) {
            int c = tid + i * 256, r = c >> 3, cb = (c & 7) << 4;
            cp16(sa + r * ROWB + cb, Ag + (size_t)r * rs + gk + cb);
        }
#pragma unroll
        for (int i = 0; i < 4; i++) {
            int c = tid + i * 256, r = c >> 3, cb = (c & 7) << 4;
            cp16(sb2 + r * ROWB + cb, Bg + (size_t)r * rs + gk + cb);
        }
    };

    const int KT = K >> 6;
    load_stage(0, 0); CP_COMMIT();
    load_stage(1, 1); CP_COMMIT();

    int buf = 0;
    for (int kt = 0; kt < KT; kt++) {
        CP_WAIT1();
        __syncthreads();
        if (kt + 2 < KT) {
            int nbuf = buf + 2; if (nbuf >= 3) nbuf -= 3;
            load_stage(nbuf, kt + 2);
        }
        CP_COMMIT();
        const uint32_t ab = smb + buf * STAGE, bb = ab + MT * ROWB;
#pragma unroll
        for (int ks = 0; ks < 4; ks++) {
            uint32_t a[FM][4];
#pragma unroll
            for (int f = 0; f < FM; f++) ldsm4(a[f], ab + a_off[f] + ks * 32);
#pragma unroll
            for (int pi = 0; pi < 2; pi++) {
                uint32_t b[4];
                ldsm4(b, bb + b_off[pi] + ks * 32);
#pragma unroll
                for (int f = 0; f < FM; f++) {
                    mma16816(acc[f][2 * pi],     a[f], b[0], b[1]);
                    mma16816(acc[f][2 * pi + 1], a[f], b[2], b[3]);
                }
            }
        }
        buf = (buf == 2) ? 0 : buf + 1;
    }

    GDC_TRIGGER();

    const int erow = lane >> 2, ecol = (lane & 3) * 2;
#pragma unroll
    for (int f = 0; f < FM; f++) {
#pragma unroll
        for (int ni = 0; ni < 4; ni++) {
            float* c = acc[f][ni];
            int col = bn + wn + ni * 8 + ecol;
#pragma unroll
            for (int half = 0; half < 2; half++) {
                int row = bm + wm + f * 16 + erow + half * 8;
                float vx = c[half * 2 + 0];
                float vy = c[half * 2 + 1];
                if (MODE == 2) {
                    int sec = col >> 10, cc = col & 1023;
                    int head = cc >> 6, d = cc & 63;
                    __half2* dst;
                    if (sec == 0) {
                        vx *= 0.125f; vy *= 0.125f;
                        dst = (__half2*)(g_q + (((size_t)head * S + row) << 6) + d);
                    } else if (sec == 1) {
                        dst = (__half2*)(g_k + (((size_t)head * S + row) << 6) + d);
                    } else {
                        dst = (__half2*)(g_v + (((size_t)head * S + row) << 6) + d);
                    }
                    *dst = __halves2half2(__float2half_rn(vx), __float2half_rn(vy));
                } else {
                    if (bias)  { vx += bias[col]; vy += bias[col + 1]; }
                    if (relu)  { vx = fmaxf(vx, 0.f); vy = fmaxf(vy, 0.f); }
                    if (MODE == 1) {
                        *(__half2*)(Cs + (size_t)row * N + col) =
                            __halves2half2(__float2half_rn(vx), __float2half_rn(vy));
                    } else {
                        if (residual) {
                            const float2 rv = *(const float2*)(residual + (size_t)row * N + col);
                            vx += rv.x; vy += rv.y;
                        }
                        float2 o; o.x = vx; o.y = vy;
                        *(float2*)(C + (size_t)row * N + col) = o;
                    }
                }
            }
        }
    }
}

// ------------- tensor-core flash attention, fp16 single-term ----------------
// Q/K/P/V rows: 144B stride (128B data + 16B pad)
#define A_Q    0u
#define A_K    9216u
#define A_P    18432u
#define A_V    27648u
#define A_PS   36864u
#define A_CORR 54272u
#define A_LROW 54528u
#define ATTN_SMEM_BYTES 54784

__global__ __launch_bounds__(256) void attn_kernel(__half* __restrict__ a3) {
    extern __shared__ char smem[];
    const uint32_t sb = smem_u32(smem);
    float* Ps     = (float*)(smem + A_PS);
    float* corr_s = (float*)(smem + A_CORR);
    float* lrow   = (float*)(smem + A_LROW);

    const int h  = blockIdx.y;
    const int q0 = blockIdx.x * 64;
    const int tid = threadIdx.x, lane = tid & 31, wid = tid >> 5;

    GDC_WAIT();

    // ---- Q tile: 64 rows x 128B direct copy ----
    const char* gqh = (const char*)(g_q + (((size_t)h * S + q0) << 6));
#pragma unroll
    for (int i = 0; i < 2; i++) {
        int idx = tid + i * 256;
        int r = idx >> 3, c = idx & 7;
        *(uint4*)(smem + A_Q + r * 144 + c * 16) = *(const uint4*)(gqh + r * 128 + c * 16);
    }

    const int wm = (wid >> 1) * 16;
    const int wn = (wid & 1) * 32;
    const int erow = lane >> 2, ecol = (lane & 3) * 2;

    const uint32_t aq_off = sb + A_Q + (wm + (lane & 15)) * 144 + ((lane >> 4) * 16);
    const uint32_t ap_off = sb + A_P + (wm + (lane & 15)) * 144 + ((lane >> 4) * 16);
    uint32_t bk_off[2], bv_off[2];
#pragma unroll
    for (int pi = 0; pi < 2; pi++) {
        int row = wn + pi * 16 + (lane & 7) + ((lane >> 4) << 3);
        bk_off[pi] = sb + A_K + row * 144 + (((lane >> 3) & 1) * 16);
        int vrow = (lane & 7) + (((lane >> 3) & 1) << 3);
        bv_off[pi] = sb + A_V + vrow * 144 + (wn + pi * 16) * 2 + ((lane >> 4) * 16);
    }

    const int qbase = tid >> 4, kbase = tid & 15;

    float m[4], l[4];
#pragma unroll
    for (int i = 0; i < 4; i++) { m[i] = -1e30f; l[i] = 0.0f; }
    float acc[4][4];
#pragma unroll
    for (int ni = 0; ni < 4; ni++)
#pragma unroll
        for (int j = 0; j < 4; j++) acc[ni][j] = 0.0f;

    int jlo, jhi;
    if (q0 < 64) { jlo = 0; jhi = 31; }
    else {
        int lo = q0 - 256; jlo = lo > 0 ? (lo >> 6) : 0;
        int hi = (q0 + 63 + 256) >> 6; jhi = hi < 31 ? hi : 31;
    }
    const bool extra0 = (q0 >= 64) && (jlo > 0);
    const int ntiles = (jhi - jlo + 1) + (extra0 ? 1 : 0);

    __syncthreads();

    for (int t = 0; t < ntiles; t++) {
        int jt = extra0 ? (t == 0 ? 0 : (jlo + t - 1)) : (jlo + t);
        int k0 = jt * 64;

        // ---- K, V tiles: 64 rows x 128B direct copies ----
        const char* gkh = (const char*)(g_k + (((size_t)h * S + k0) << 6));
        const char* gvh = (const char*)(g_v + (((size_t)h * S + k0) << 6));
#pragma unroll
        for (int i = 0; i < 2; i++) {
            int idx = tid + i * 256;
            int r = idx >> 3, c = idx & 7;
            *(uint4*)(smem + A_K + r * 144 + c * 16) = *(const uint4*)(gkh + r * 128 + c * 16);
            *(uint4*)(smem + A_V + r * 144 + c * 16) = *(const uint4*)(gvh + r * 128 + c * 16);
        }
        __syncthreads();

        // ---- S = Q K^T (k = 64) ----
        float cq[4][4];
#pragma unroll
        for (int ni = 0; ni < 4; ni++)
#pragma unroll
            for (int j = 0; j < 4; j++) cq[ni][j] = 0.0f;
#pragma unroll
        for (int ks = 0; ks < 4; ks++) {
            uint32_t a[4];
            ldsm4(a, aq_off + ks * 32);
#pragma unroll
            for (int pi = 0; pi < 2; pi++) {
                uint32_t b[4];
                ldsm4(b, bk_off[pi] + ks * 32);
                mma16816(cq[2 * pi],     a, b[0], b[1]);
                mma16816(cq[2 * pi + 1], a, b[2], b[3]);
            }
        }
#pragma unroll
        for (int ni = 0; ni < 4; ni++) {
            int col = wn + ni * 8 + ecol;
            float2 s0; s0.x = cq[ni][0]; s0.y = cq[ni][1];
            float2 s1; s1.x = cq[ni][2]; s1.y = cq[ni][3];
            *(float2*)(Ps + (wm + erow) * 68 + col)     = s0;
            *(float2*)(Ps + (wm + erow + 8) * 68 + col) = s1;
        }
        __syncthreads();

        // ---- mask + online softmax ----
        const bool tileAll = (q0 < 64) || (k0 < 64);
#pragma unroll
        for (int i = 0; i < 4; i++) {
            int qr = qbase + 16 * i;
            int gi = q0 + qr;
            float sreg[4];
#pragma unroll
            for (int j = 0; j < 4; j++) {
                sreg[j] = Ps[qr * 68 + kbase + 16 * j];
                if (!tileAll) {
                    int gj = k0 + kbase + 16 * j;
                    int diff = gi - gj; if (diff < 0) diff = -diff;
                    if (diff > 256) sreg[j] = -1e30f;
                }
            }
            float mx = fmaxf(fmaxf(sreg[0], sreg[1]), fmaxf(sreg[2], sreg[3]));
#pragma unroll
            for (int off = 8; off > 0; off >>= 1)
                mx = fmaxf(mx, __shfl_xor_sync(0xffffffffu, mx, off, 16));
            float mnew = fmaxf(m[i], mx);
            float corr = __expf(m[i] - mnew);
            float psum = 0.0f;
#pragma unroll
            for (int j = 0; j < 4; j++) {
                float p = __expf(sreg[j] - mnew);
                sreg[j] = p;
                psum += p;
            }
#pragma unroll
            for (int off = 8; off > 0; off >>= 1)
                psum += __shfl_xor_sync(0xffffffffu, psum, off, 16);
            l[i] = l[i] * corr + psum;
            m[i] = mnew;
            char* prow = smem + A_P + qr * 144;
#pragma unroll
            for (int j = 0; j < 4; j++) {
                int col = kbase + 16 * j;
                *(__half*)(prow + 2 * col) = __float2half_rn(sreg[j]);
            }
            if (kbase == 0) corr_s[qr] = corr;
        }
        __syncthreads();

        // ---- ctx: P @ V (k = 64 rows) ----
        float cv[4][4];
#pragma unroll
        for (int ni = 0; ni < 4; ni++)
#pragma unroll
            for (int j = 0; j < 4; j++) cv[ni][j] = 0.0f;
#pragma unroll
        for (int ks = 0; ks < 4; ks++) {
            uint32_t a[4];
            ldsm4(a, ap_off + ks * 32);
#pragma unroll
            for (int pi = 0; pi < 2; pi++) {
                uint32_t b[4];
                ldsm4t(b, bv_off[pi] + ks * 16 * 144);
                mma16816(cv[2 * pi],     a, b[0], b[1]);
                mma16816(cv[2 * pi + 1], a, b[2], b[3]);
            }
        }
        float c0 = corr_s[wm + erow], c1 = corr_s[wm + erow + 8];
#pragma unroll
        for (int ni = 0; ni < 4; ni++) {
            acc[ni][0] = acc[ni][0] * c0 + cv[ni][0];
            acc[ni][1] = acc[ni][1] * c0 + cv[ni][1];
            acc[ni][2] = acc[ni][2] * c1 + cv[ni][2];
            acc[ni][3] = acc[ni][3] * c1 + cv[ni][3];
        }
        __syncthreads();
    }

    GDC_TRIGGER();

    if (kbase == 0) {
#pragma unroll
        for (int i = 0; i < 4; i++) lrow[qbase + 16 * i] = l[i];
    }
    __syncthreads();

    float inv0 = 1.0f / lrow[wm + erow];
    float inv1 = 1.0f / lrow[wm + erow + 8];
    int row0 = q0 + wm + erow, row1 = row0 + 8;
    const int qcol = h * HD;
#pragma unroll
    for (int ni = 0; ni < 4; ni++) {
        int col = wn + ni * 8 + ecol;
        __half h0 = __float2half_rn(acc[ni][0] * inv0);
        __half h1 = __float2half_rn(acc[ni][1] * inv0);
        __half h2 = __float2half_rn(acc[ni][2] * inv1);
        __half h3 = __float2half_rn(acc[ni][3] * inv1);
        *(__half2*)(a3 + (size_t)row0 * D + qcol + col) = __halves2half2(h0, h1);
        *(__half2*)(a3 + (size_t)row1 * D + qcol + col) = __halves2half2(h2, h3);
    }
}

// ---------------- PDL launch helper ----------------
template<typename F, typename... Args>
static inline void pdl(F f, dim3 g, dim3 b, size_t smem, Args... args) {
    cudaLaunchConfig_t cfg = {};
    cfg.gridDim = g; cfg.blockDim = b; cfg.dynamicSmemBytes = smem; cfg.stream = 0;
    cudaLaunchAttribute at[1];
    at[0].id = cudaLaunchAttributeProgrammaticStreamSerialization;
    at[0].val.programmaticStreamSerializationAllowed = 1;
    cfg.attrs = at; cfg.numAttrs = 1;
    cudaLaunchKernelEx(&cfg, f, args...);
}

// ---------------- launch ----------------
extern "C" void kernel_launch(void* const* d_in, const int* in_sizes, int n_in,
                              void* d_out, int out_size) {
    const int*   ids    = (const int*)d_in[0];
    const float* emb    = (const float*)d_in[2];
    const float* wq     = (const float*)d_in[3];
    const float* wk     = (const float*)d_in[4];
    const float* wv     = (const float*)d_in[5];
    const float* wo     = (const float*)d_in[6];
    const float* ln1_s  = (const float*)d_in[7];
    const float* ln1_b  = (const float*)d_in[8];
    const float* ln2_s  = (const float*)d_in[9];
    const float* ln2_b  = (const float*)d_in[10];
    const float* w1     = (const float*)d_in[11];
    const float* b1     = (const float*)d_in[12];
    const float* w2     = (const float*)d_in[13];
    const float* b2     = (const float*)d_in[14];
    const float* lnf_s  = (const float*)d_in[15];
    const float* lnf_b  = (const float*)d_in[16];
    float* out = (float*)d_out;

    void *px, *pa3, *py3, *pwT;
    cudaGetSymbolAddress(&px, g_x);
    cudaGetSymbolAddress(&pa3, g_a3);
    cudaGetSymbolAddress(&py3, g_y3);
    cudaGetSymbolAddress(&pwT, g_wT);
    float* x = (float*)px;
    __half* a3 = (__half*)pa3;
    __half* y3 = (__half*)py3;
    __half* wT = (__half*)pwT;

    cudaFuncSetAttribute(attn_kernel, cudaFuncAttributeMaxDynamicSharedMemorySize, ATTN_SMEM_BYTES);
    const int GS128 = 3 * 256 * 144;
    const int GS64  = 3 * 192 * 144;
    cudaFuncSetAttribute((gemm_tpl<128, 1>), cudaFuncAttributeMaxDynamicSharedMemorySize, GS128);
    cudaFuncSetAttribute((gemm_tpl<128, 2>), cudaFuncAttributeMaxDynamicSharedMemorySize, GS128);
    cudaFuncSetAttribute((gemm_tpl<64, 0>),  cudaFuncAttributeMaxDynamicSharedMemorySize, GS64);

    pdl(embed_kernel, dim3(S), dim3(256), 0, ids, emb, x);
    pdl(convW4_all, dim3(32, 32, 16), dim3(256), 0, wq, wk, wv, wo, wT);
    pdl(ln_half_kernel, dim3(S), dim3(256), 0, x, ln1_s, ln1_b, a3);

    for (int l = 0; l < LAY; l++) {
        __half* wL = wT + (size_t)l * WT_LAYER;
        if (l > 0)
            pdl(ln_half_kernel, dim3(S), dim3(256), 0,
                x, ln1_s + l * D, ln1_b + l * D, a3);
        pdl(gemm_tpl<128, 2>, dim3(QKVW / 128, S / 128), dim3(256), GS128,
            a3, (const __half*)(wL + WT_QKV), (float*)nullptr, (__half*)nullptr,
            QKVW, D, (const float*)nullptr, (const float*)nullptr, 0);
        pdl(attn_kernel, dim3(S / 64, H), dim3(256), ATTN_SMEM_BYTES, a3);
        if (l == 0)
            pdl(convW12_all, dim3(4096, 8), dim3(256), 0, w1, w2, wT);
        pdl(gemm_tpl<64, 0>, dim3(D / 128, S / 64), dim3(256), GS64,
            a3, (const __half*)(wL + WT_WO), x, (__half*)nullptr,
            D, D, (const float*)nullptr, (const float*)x, 0);
        pdl(ln_half_kernel, dim3(S), dim3(256), 0,
            x, ln2_s + l * D, ln2_b + l * D, a3);
        pdl(gemm_tpl<128, 1>, dim3(MM / 128, S / 128), dim3(256), GS128,
            a3, (const __half*)(wL + WT_W1), (float*)nullptr, y3,
            MM, D, b1 + (size_t)l * MM, (const float*)nullptr, 1);
        pdl(gemm_tpl<64, 0>, dim3(D / 128, S / 64), dim3(256), GS64,
            y3, (const __half*)(wL + WT_W2), x, (__half*)nullptr,
            D, MM, b2 + (size_t)l * D, (const float*)x, 0);
    }
    pdl(ln_kernel, dim3(S), dim3(256), 0, x, lnf_s, lnf_b, out);
}